// round 12
// baseline (speedup 1.0000x reference)
#include <cuda_runtime.h>
#include <cuda_bf16.h>
#include <cstdint>

#define BATCH 8
#define SEQ 2048
#define CDIM 512
#define HEADS 4
#define HDIM 128
#define ROWS_TOTAL (BATCH * SEQ)
#define SCALE_F 0.04419417382415922f   // 1/sqrt(512)

// ---------------- bf16 hi/lo split scratch (no cudaMalloc allowed) ----------
__device__ __nv_bfloat16 g_f1h[ROWS_TOTAL * CDIM], g_f1l[ROWS_TOTAL * CDIM];
__device__ __nv_bfloat16 g_f2h[ROWS_TOTAL * CDIM], g_f2l[ROWS_TOTAL * CDIM];
__device__ __nv_bfloat16 g_wqh[CDIM * CDIM],       g_wql[CDIM * CDIM];
__device__ __nv_bfloat16 g_wph[CDIM * CDIM],       g_wpl[CDIM * CDIM];
__device__ __nv_bfloat16 g_qh [ROWS_TOTAL * CDIM], g_ql [ROWS_TOTAL * CDIM];
__device__ __nv_bfloat16 g_kvh[ROWS_TOTAL * CDIM], g_kvl[ROWS_TOTAL * CDIM];
__device__ __nv_bfloat16 g_xh [ROWS_TOTAL * CDIM], g_xl [ROWS_TOTAL * CDIM];

// ---------------------------------------------------------------------------
__device__ __forceinline__ uint32_t smem_u32(const void* p) {
    uint32_t a;
    asm("{ .reg .u64 t; cvta.to.shared.u64 t, %1; cvt.u32.u64 %0, t; }"
        : "=r"(a) : "l"(p));
    return a;
}

#define CP16(dst, src)                                                        \
    asm volatile("cp.async.cg.shared.global [%0], [%1], 16;"                  \
                 :: "r"(dst), "l"(src) : "memory")
#define CP_COMMIT() asm volatile("cp.async.commit_group;" ::: "memory")
#define CP_WAIT1()  asm volatile("cp.async.wait_group 1;" ::: "memory")
#define CP_WAIT0()  asm volatile("cp.async.wait_group 0;" ::: "memory")
#define BARG(id)                                                              \
    asm volatile("bar.sync %0, 256;" :: "r"(id) : "memory")

#define LDSM_X4(R0, R1, R2, R3, A)                                            \
    asm volatile("ldmatrix.sync.aligned.m8n8.x4.shared.b16 {%0,%1,%2,%3}, [%4];" \
                 : "=r"(R0), "=r"(R1), "=r"(R2), "=r"(R3) : "r"(A))
#define LDSM_X4T(R0, R1, R2, R3, A)                                           \
    asm volatile("ldmatrix.sync.aligned.m8n8.x4.trans.shared.b16 {%0,%1,%2,%3}, [%4];" \
                 : "=r"(R0), "=r"(R1), "=r"(R2), "=r"(R3) : "r"(A))
#define MMA16816(D, A0, A1, A2, A3, B0, B1)                                   \
    asm volatile("mma.sync.aligned.m16n8k16.row.col.f32.bf16.bf16.f32 "       \
                 "{%0,%1,%2,%3}, {%4,%5,%6,%7}, {%8,%9}, {%0,%1,%2,%3};"      \
                 : "+f"((D)[0]), "+f"((D)[1]), "+f"((D)[2]), "+f"((D)[3])     \
                 : "r"(A0), "r"(A1), "r"(A2), "r"(A3), "r"(B0), "r"(B1))

__device__ __forceinline__ uint32_t b2u(__nv_bfloat162 h) { return *(uint32_t*)&h; }

// ============================ conversion: fp32 -> bf16 hi/lo =================
__global__ void conv_split(const float4* __restrict__ src, uint2* __restrict__ h,
                           uint2* __restrict__ l, int n4) {
    for (int i = blockIdx.x * blockDim.x + threadIdx.x; i < n4;
         i += gridDim.x * blockDim.x) {
        float4 v = src[i];
        __nv_bfloat162 h0 = __floats2bfloat162_rn(v.x, v.y);
        __nv_bfloat162 h1 = __floats2bfloat162_rn(v.z, v.w);
        __nv_bfloat162 l0 = __floats2bfloat162_rn(v.x - __bfloat162float(h0.x),
                                                  v.y - __bfloat162float(h0.y));
        __nv_bfloat162 l1 = __floats2bfloat162_rn(v.z - __bfloat162float(h1.x),
                                                  v.w - __bfloat162float(h1.y));
        h[i] = make_uint2(b2u(h0), b2u(h1));
        l[i] = make_uint2(b2u(l0), b2u(l1));
    }
}

// ============================ GEMM + bias ====================================
// C[16384,512] = A @ W + bias; inputs pre-split bf16; split-bf16 x3 MMAs.
// CTA tile 256x128, 512 threads (16 warps, warp tile 64x32), K-chunk 64,
// cp.async double-buffered.
#define ASTR 144
#define A_SPLIT 36864            // 256*144
#define A_STAGE (2 * A_SPLIT)    // hi+lo
#define WSTR 272
#define W_SPLIT 17408            // 64*272
#define W_STAGE (2 * W_SPLIT)
#define GW_BASE (2 * A_STAGE)    // 147456
#define G_SMEM (GW_BASE + 2 * W_STAGE)   // 217088

__global__ void __launch_bounds__(512, 1)
gemm_tc(const __nv_bfloat16* __restrict__ Ah, const __nv_bfloat16* __restrict__ Al,
        const __nv_bfloat16* __restrict__ Wh, const __nv_bfloat16* __restrict__ Wl,
        const float* __restrict__ bias, float* __restrict__ C,
        __nv_bfloat16* __restrict__ Ch, __nv_bfloat16* __restrict__ Cl,
        float scale, int mode) {
    extern __shared__ char sm[];
    const uint32_t sb = smem_u32(sm);
    const int tid = threadIdx.x, l = tid & 31, wid = tid >> 5;
    const int row0 = blockIdx.y * 256, col0 = blockIdx.x * 128;
    const int wm = wid >> 2, wn = wid & 3;

    const uint32_t a_boff = (uint32_t)(wm * 64 + (l & 15)) * ASTR + ((l >> 4) & 1) * 16;
    const uint32_t b_boff = (uint32_t)((l & 7) + ((l >> 3) & 1) * 8) * WSTR +
                            ((l >> 4) & 1) * 16 + (uint32_t)wn * 64;

    auto issue = [&](int ch, int buf) {
#pragma unroll
        for (int t = 0; t < 4; t++) {
            int idx = tid + t * 512, r = idx >> 3, ai = idx & 7;
            uint32_t d = sb + buf * A_STAGE + (uint32_t)r * ASTR + ai * 16;
            const __nv_bfloat16* s = Ah + (size_t)(row0 + r) * CDIM + ch * 64 + ai * 8;
            CP16(d, s);
            CP16(d + A_SPLIT, Al + (s - Ah));
        }
#pragma unroll
        for (int t = 0; t < 2; t++) {
            int idx = tid + t * 512, r = idx >> 4, wi = idx & 15;
            uint32_t d = sb + GW_BASE + buf * W_STAGE + (uint32_t)r * WSTR + wi * 16;
            const __nv_bfloat16* s = Wh + (size_t)(ch * 64 + r) * CDIM + col0 + wi * 8;
            CP16(d, s);
            CP16(d + W_SPLIT, Wl + (s - Wh));
        }
        CP_COMMIT();
    };

    float acc[4][4][4];
#pragma unroll
    for (int i = 0; i < 4; i++)
#pragma unroll
        for (int j = 0; j < 4; j++)
#pragma unroll
            for (int e = 0; e < 4; e++) acc[i][j][e] = 0.0f;

    issue(0, 0);
    for (int ch = 0; ch < 8; ch++) {
        const int cur = ch & 1;
        if (ch < 7) issue(ch + 1, cur ^ 1);
        if (ch < 7) CP_WAIT1(); else CP_WAIT0();
        __syncthreads();

        const uint32_t AH = sb + cur * A_STAGE, AL = AH + A_SPLIT;
        const uint32_t WH = sb + GW_BASE + cur * W_STAGE, WL = WH + W_SPLIT;
#pragma unroll
        for (int t = 0; t < 4; t++) {
            uint32_t aH[4][4], aL[4][4];
#pragma unroll
            for (int i = 0; i < 4; i++) {
                LDSM_X4(aH[i][0], aH[i][1], aH[i][2], aH[i][3],
                        AH + a_boff + i * 16 * ASTR + t * 32);
                LDSM_X4(aL[i][0], aL[i][1], aL[i][2], aL[i][3],
                        AL + a_boff + i * 16 * ASTR + t * 32);
            }
#pragma unroll
            for (int c2 = 0; c2 < 2; c2++) {
                uint32_t bh0, bh1, bh2, bh3, bl0, bl1, bl2, bl3;
                LDSM_X4T(bh0, bh1, bh2, bh3, WH + b_boff + t * 16 * WSTR + c2 * 32);
                LDSM_X4T(bl0, bl1, bl2, bl3, WL + b_boff + t * 16 * WSTR + c2 * 32);
#pragma unroll
                for (int i = 0; i < 4; i++) {
                    MMA16816(acc[i][c2 * 2 + 0], aH[i][0], aH[i][1], aH[i][2], aH[i][3], bh0, bh1);
                    MMA16816(acc[i][c2 * 2 + 1], aH[i][0], aH[i][1], aH[i][2], aH[i][3], bh2, bh3);
                    MMA16816(acc[i][c2 * 2 + 0], aH[i][0], aH[i][1], aH[i][2], aH[i][3], bl0, bl1);
                    MMA16816(acc[i][c2 * 2 + 1], aH[i][0], aH[i][1], aH[i][2], aH[i][3], bl2, bl3);
                    MMA16816(acc[i][c2 * 2 + 0], aL[i][0], aL[i][1], aL[i][2], aL[i][3], bh0, bh1);
                    MMA16816(acc[i][c2 * 2 + 1], aL[i][0], aL[i][1], aL[i][2], aL[i][3], bh2, bh3);
                }
            }
        }
        __syncthreads();
    }

    // epilogue: direct stores with bias (+ optional scale & bf16 split)
#pragma unroll
    for (int i = 0; i < 4; i++)
#pragma unroll
        for (int j = 0; j < 4; j++) {
            int r = row0 + wm * 64 + i * 16 + (l >> 2);
            int c = col0 + wn * 32 + j * 8 + (l & 3) * 2;
            float2 bb = *(const float2*)(bias + c);
            float v0 = acc[i][j][0] + bb.x, v1 = acc[i][j][1] + bb.y;
            float v2 = acc[i][j][2] + bb.x, v3 = acc[i][j][3] + bb.y;
            if (mode == 0) {
                *(float2*)(C + (size_t)r * CDIM + c)       = make_float2(v0, v1);
                *(float2*)(C + (size_t)(r + 8) * CDIM + c) = make_float2(v2, v3);
            } else {
                v0 *= scale; v1 *= scale; v2 *= scale; v3 *= scale;
                __nv_bfloat162 h0 = __floats2bfloat162_rn(v0, v1);
                __nv_bfloat162 h1 = __floats2bfloat162_rn(v2, v3);
                __nv_bfloat162 l0 = __floats2bfloat162_rn(v0 - __bfloat162float(h0.x),
                                                          v1 - __bfloat162float(h0.y));
                __nv_bfloat162 l1 = __floats2bfloat162_rn(v2 - __bfloat162float(h1.x),
                                                          v3 - __bfloat162float(h1.y));
                *(uint32_t*)(Ch + (size_t)r * CDIM + c)       = b2u(h0);
                *(uint32_t*)(Ch + (size_t)(r + 8) * CDIM + c) = b2u(h1);
                *(uint32_t*)(Cl + (size_t)r * CDIM + c)       = b2u(l0);
                *(uint32_t*)(Cl + (size_t)(r + 8) * CDIM + c) = b2u(l1);
            }
        }
}

// ============================ Fused attention ================================
// CTA per (b,h,128-q tile), 512 threads. Warps 0-7 = group 0 (even KV tiles),
// warps 8-15 = group 1 (odd tiles); per-group named barriers + cp.async
// double buffers. Q is loaded by ALL threads, so it gets its own commit group
// and a FULL __syncthreads() before the first read (the R9 race). KV tiles
// are group-local, so group-local barriers suffice for them.
#define QSTR 272
#define Q_SPLIT 34816            // 128*272
#define KSTR 272
#define K_SPLIT 17408            // 64*272
#define AK_BASE (2 * Q_SPLIT)    // 69632
#define AT_SMEM (AK_BASE + 8 * K_SPLIT)   // 208896

__global__ void __launch_bounds__(512, 1)
attn_tc(const __nv_bfloat16* __restrict__ Qh, const __nv_bfloat16* __restrict__ Ql,
        const __nv_bfloat16* __restrict__ KVh, const __nv_bfloat16* __restrict__ KVl,
        __nv_bfloat16* __restrict__ Xh, __nv_bfloat16* __restrict__ Xl) {
    extern __shared__ char sm[];
    const uint32_t sb = smem_u32(sm);
    const int tid = threadIdx.x, l = tid & 31, wid = tid >> 5;
    const int g = wid >> 3, wg = wid & 7, gtid = tid & 255;
    const int b = blockIdx.z, h = blockIdx.y, n0 = blockIdx.x * 128;

    const uint32_t qa_boff = (uint32_t)(wg * 16 + (l & 15)) * QSTR + ((l >> 4) & 1) * 16;
    const uint32_t kb_boff = (uint32_t)((l & 7) + ((l >> 4) & 1) * 8) * KSTR +
                             ((l >> 3) & 1) * 16;
    const uint32_t vb_boff = (uint32_t)((l & 7) + ((l >> 3) & 1) * 8) * KSTR +
                             ((l >> 4) & 1) * 16;
    const size_t kvrow0 = (size_t)b * SEQ * CDIM + h * HDIM;

    auto issue_kv = [&](int j, int buf) {
        const int m = 2 * j + g;
        const uint32_t slot = sb + AK_BASE + (uint32_t)(g * 2 + buf) * (2 * K_SPLIT);
#pragma unroll
        for (int t = 0; t < 4; t++) {
            int idx = gtid + t * 256, r = idx >> 4, i = idx & 15;
            uint32_t d = slot + (uint32_t)r * KSTR + i * 16;
            const __nv_bfloat16* s = KVh + kvrow0 + (size_t)(m * 64 + r) * CDIM + i * 8;
            CP16(d, s);
            CP16(d + K_SPLIT, KVl + (s - KVh));
        }
        CP_COMMIT();
    };

    // Q tile (both splits) via cp.async — OWN commit group (cross-group data!)
#pragma unroll
    for (int t = 0; t < 8; t++) {
        int idx = tid + t * 512;
        int a = idx >> 11, r = (idx >> 4) & 127, i = idx & 15;
        uint32_t d = sb + a * Q_SPLIT + (uint32_t)r * QSTR + i * 16;
        const __nv_bfloat16* base = a ? Ql : Qh;
        CP16(d, base + ((size_t)(b * SEQ + n0 + r)) * CDIM + h * HDIM + i * 8);
    }
    CP_COMMIT();        // group: Q only
    issue_kv(0, 0);     // group: KV0 (group-local)

    // Drain Q (leave KV0 in flight), then make it visible to BOTH groups.
    CP_WAIT1();
    __syncthreads();    // <-- the fix: full-CTA barrier before any Q read

    float oacc[16][4];
#pragma unroll
    for (int n = 0; n < 16; n++)
#pragma unroll
        for (int e = 0; e < 4; e++) oacc[n][e] = 0.0f;
    float lsum0 = 0.0f, lsum1 = 0.0f;

    for (int j = 0; j < 16; j++) {
        const int cur = j & 1;
        if (j < 15) issue_kv(j + 1, cur ^ 1);
        if (j < 15) CP_WAIT1(); else CP_WAIT0();
        BARG(g + 1);

        const uint32_t KH = sb + AK_BASE + (uint32_t)(g * 2 + cur) * (2 * K_SPLIT);
        const uint32_t KL = KH + K_SPLIT;

        // ---- S = Qs . K^T  (16 x 64 per warp) ----
        float sacc[8][4];
#pragma unroll
        for (int n = 0; n < 8; n++)
#pragma unroll
            for (int e = 0; e < 4; e++) sacc[n][e] = 0.0f;
#pragma unroll
        for (int t = 0; t < 8; t++) {
            uint32_t aH0, aH1, aH2, aH3, aL0, aL1, aL2, aL3;
            LDSM_X4(aH0, aH1, aH2, aH3, sb + qa_boff + t * 32);
            LDSM_X4(aL0, aL1, aL2, aL3, sb + Q_SPLIT + qa_boff + t * 32);
#pragma unroll
            for (int jj = 0; jj < 4; jj++) {
                uint32_t bh0, bh1, bh2, bh3, bl0, bl1, bl2, bl3;
                LDSM_X4(bh0, bh1, bh2, bh3, KH + kb_boff + jj * 16 * KSTR + t * 32);
                LDSM_X4(bl0, bl1, bl2, bl3, KL + kb_boff + jj * 16 * KSTR + t * 32);
                MMA16816(sacc[2 * jj + 0], aH0, aH1, aH2, aH3, bh0, bh1);
                MMA16816(sacc[2 * jj + 1], aH0, aH1, aH2, aH3, bh2, bh3);
                MMA16816(sacc[2 * jj + 0], aH0, aH1, aH2, aH3, bl0, bl1);
                MMA16816(sacc[2 * jj + 1], aH0, aH1, aH2, aH3, bl2, bl3);
                MMA16816(sacc[2 * jj + 0], aL0, aL1, aL2, aL3, bh0, bh1);
                MMA16816(sacc[2 * jj + 1], aL0, aL1, aL2, aL3, bh2, bh3);
            }
        }

        // ---- softmax (no max-sub); P hi/lo fragments overwrite sacc regs ----
#pragma unroll
        for (int n = 0; n < 8; n++) {
            float p0 = __expf(sacc[n][0]);
            float p1 = __expf(sacc[n][1]);
            float p2 = __expf(sacc[n][2]);
            float p3 = __expf(sacc[n][3]);
            lsum0 += p0 + p1;
            lsum1 += p2 + p3;
            __nv_bfloat162 h0 = __floats2bfloat162_rn(p0, p1);
            __nv_bfloat162 h1 = __floats2bfloat162_rn(p2, p3);
            __nv_bfloat162 l0 = __floats2bfloat162_rn(p0 - __bfloat162float(h0.x),
                                                      p1 - __bfloat162float(h0.y));
            __nv_bfloat162 l1 = __floats2bfloat162_rn(p2 - __bfloat162float(h1.x),
                                                      p3 - __bfloat162float(h1.y));
            sacc[n][0] = __uint_as_float(b2u(h0));
            sacc[n][1] = __uint_as_float(b2u(h1));
            sacc[n][2] = __uint_as_float(b2u(l0));
            sacc[n][3] = __uint_as_float(b2u(l1));
        }

        // ---- O += P . V  (V = same KV tile, trans view) ----
#pragma unroll
        for (int tp = 0; tp < 4; tp++) {
            uint32_t h0 = __float_as_uint(sacc[2 * tp][0]);
            uint32_t h1 = __float_as_uint(sacc[2 * tp][1]);
            uint32_t h2 = __float_as_uint(sacc[2 * tp + 1][0]);
            uint32_t h3 = __float_as_uint(sacc[2 * tp + 1][1]);
            uint32_t lo0 = __float_as_uint(sacc[2 * tp][2]);
            uint32_t lo1 = __float_as_uint(sacc[2 * tp][3]);
            uint32_t lo2 = __float_as_uint(sacc[2 * tp + 1][2]);
            uint32_t lo3 = __float_as_uint(sacc[2 * tp + 1][3]);
#pragma unroll
            for (int dd = 0; dd < 8; dd++) {
                uint32_t vh0, vh1, vh2, vh3, vl0, vl1, vl2, vl3;
                LDSM_X4T(vh0, vh1, vh2, vh3, KH + vb_boff + tp * 16 * KSTR + dd * 32);
                LDSM_X4T(vl0, vl1, vl2, vl3, KL + vb_boff + tp * 16 * KSTR + dd * 32);
                MMA16816(oacc[2 * dd + 0], h0, h1, h2, h3, vh0, vh1);
                MMA16816(oacc[2 * dd + 1], h0, h1, h2, h3, vh2, vh3);
                MMA16816(oacc[2 * dd + 0], h0, h1, h2, h3, vl0, vl1);
                MMA16816(oacc[2 * dd + 1], h0, h1, h2, h3, vl2, vl3);
                MMA16816(oacc[2 * dd + 0], lo0, lo1, lo2, lo3, vh0, vh1);
                MMA16816(oacc[2 * dd + 1], lo0, lo1, lo2, lo3, vh2, vh3);
            }
        }
        BARG(g + 1);
    }

    // row sums across the 4 threads sharing each row
    lsum0 += __shfl_xor_sync(0xffffffffu, lsum0, 1);
    lsum0 += __shfl_xor_sync(0xffffffffu, lsum0, 2);
    lsum1 += __shfl_xor_sync(0xffffffffu, lsum1, 1);
    lsum1 += __shfl_xor_sync(0xffffffffu, lsum1, 2);

    // ---- combine groups ----
    float* stage = (float*)(sm + AK_BASE);
    float* ls = stage + 128 * 132;
    const int r0 = wg * 16 + (l >> 2);

    __syncthreads();
    if (g == 1) {
#pragma unroll
        for (int n = 0; n < 16; n++) {
            int c = n * 8 + (l & 3) * 2;
            *(float2*)&stage[r0 * 132 + c]       = make_float2(oacc[n][0], oacc[n][1]);
            *(float2*)&stage[(r0 + 8) * 132 + c] = make_float2(oacc[n][2], oacc[n][3]);
        }
        if ((l & 3) == 0) { ls[r0] = lsum0; ls[r0 + 8] = lsum1; }
    }
    __syncthreads();
    if (g == 0) {
        const float inv0 = 1.0f / (lsum0 + ls[r0]);
        const float inv1 = 1.0f / (lsum1 + ls[r0 + 8]);
#pragma unroll
        for (int n = 0; n < 16; n++) {
            int c = n * 8 + (l & 3) * 2;
            float2 p0 = *(float2*)&stage[r0 * 132 + c];
            float2 p1 = *(float2*)&stage[(r0 + 8) * 132 + c];
            float v0 = (oacc[n][0] + p0.x) * inv0, v1 = (oacc[n][1] + p0.y) * inv0;
            float v2 = (oacc[n][2] + p1.x) * inv1, v3 = (oacc[n][3] + p1.y) * inv1;
            __nv_bfloat162 h0 = __floats2bfloat162_rn(v0, v1);
            __nv_bfloat162 h1 = __floats2bfloat162_rn(v2, v3);
            __nv_bfloat162 l0 = __floats2bfloat162_rn(v0 - __bfloat162float(h0.x),
                                                      v1 - __bfloat162float(h0.y));
            __nv_bfloat162 l1 = __floats2bfloat162_rn(v2 - __bfloat162float(h1.x),
                                                      v3 - __bfloat162float(h1.y));
            *(uint32_t*)(sm + r0 * QSTR + c * 2)           = b2u(h0);
            *(uint32_t*)(sm + (r0 + 8) * QSTR + c * 2)     = b2u(h1);
            *(uint32_t*)(sm + Q_SPLIT + r0 * QSTR + c * 2)       = b2u(l0);
            *(uint32_t*)(sm + Q_SPLIT + (r0 + 8) * QSTR + c * 2) = b2u(l1);
        }
    }
    __syncthreads();

    // coalesced copy-out of Xh/Xl
#pragma unroll
    for (int t = 0; t < 8; t++) {
        int idx = tid + t * 512;
        int a = idx >> 11, r = (idx >> 4) & 127, i = idx & 15;
        uint4 v = *(uint4*)(sm + a * Q_SPLIT + (uint32_t)r * QSTR + i * 16);
        __nv_bfloat16* base = a ? Xl : Xh;
        *(uint4*)(base + ((size_t)(b * SEQ + n0 + r)) * CDIM + h * HDIM + i * 8) = v;
    }
}

// ============================ launch ============================
extern "C" void kernel_launch(void* const* d_in, const int* in_sizes, int n_in,
                              void* d_out, int out_size) {
    const float* F1    = (const float*)d_in[0];
    const float* F2    = (const float*)d_in[1];
    const float* Wqkv  = (const float*)d_in[2];
    const float* bqkv  = (const float*)d_in[3];
    const float* Wproj = (const float*)d_in[4];
    const float* bproj = (const float*)d_in[5];
    float* out = (float*)d_out;

    __nv_bfloat16 *f1h, *f1l, *f2h, *f2l, *wqh, *wql, *wph, *wpl;
    __nv_bfloat16 *qh, *ql, *kvh, *kvl, *xh, *xl;
    cudaGetSymbolAddress((void**)&f1h, g_f1h); cudaGetSymbolAddress((void**)&f1l, g_f1l);
    cudaGetSymbolAddress((void**)&f2h, g_f2h); cudaGetSymbolAddress((void**)&f2l, g_f2l);
    cudaGetSymbolAddress((void**)&wqh, g_wqh); cudaGetSymbolAddress((void**)&wql, g_wql);
    cudaGetSymbolAddress((void**)&wph, g_wph); cudaGetSymbolAddress((void**)&wpl, g_wpl);
    cudaGetSymbolAddress((void**)&qh,  g_qh);  cudaGetSymbolAddress((void**)&ql,  g_ql);
    cudaGetSymbolAddress((void**)&kvh, g_kvh); cudaGetSymbolAddress((void**)&kvl, g_kvl);
    cudaGetSymbolAddress((void**)&xh,  g_xh);  cudaGetSymbolAddress((void**)&xl,  g_xl);

    cudaFuncSetAttribute(gemm_tc, cudaFuncAttributeMaxDynamicSharedMemorySize, G_SMEM);
    cudaFuncSetAttribute(attn_tc, cudaFuncAttributeMaxDynamicSharedMemorySize, AT_SMEM);

    const int NF4 = ROWS_TOTAL * CDIM / 4, NW4 = CDIM * CDIM / 4;
    conv_split<<<2048, 256>>>((const float4*)F1, (uint2*)f1h, (uint2*)f1l, NF4);
    conv_split<<<2048, 256>>>((const float4*)F2, (uint2*)f2h, (uint2*)f2l, NF4);
    conv_split<<<256, 256>>>((const float4*)Wqkv, (uint2*)wqh, (uint2*)wql, NW4);
    conv_split<<<256, 256>>>((const float4*)Wproj, (uint2*)wph, (uint2*)wpl, NW4);

    dim3 ggrid(CDIM / 128, ROWS_TOTAL / 256);   // (4, 64)
    gemm_tc<<<ggrid, 512, G_SMEM>>>(f1h, f1l, wqh, wql, bqkv, nullptr,
                                    qh, ql, SCALE_F, 1);
    gemm_tc<<<ggrid, 512, G_SMEM>>>(f2h, f2l, wqh, wql, bqkv, nullptr,
                                    kvh, kvl, 1.0f, 1);

    dim3 agrid(SEQ / 128, HEADS, BATCH);        // (16, 4, 8)
    attn_tc<<<agrid, 512, AT_SMEM>>>(qh, ql, kvh, kvl, xh, xl);

    gemm_tc<<<ggrid, 512, G_SMEM>>>(xh, xl, wph, wpl, bproj, out,
                                    nullptr, nullptr, 0.0f, 0);
}

// round 14
// speedup vs baseline: 1.2396x; 1.2396x over previous
#include <cuda_runtime.h>
#include <cuda_bf16.h>
#include <cuda_fp16.h>
#include <cstdint>

#define BATCH 8
#define SEQ 2048
#define CDIM 512
#define HEADS 4
#define HDIM 128
#define ROWS_TOTAL (BATCH * SEQ)
#define SCALE_F 0.04419417382415922f   // 1/sqrt(512)

// ---------------- scratch (no cudaMalloc allowed) ----------
__device__ __nv_bfloat16 g_f1h[ROWS_TOTAL * CDIM], g_f1l[ROWS_TOTAL * CDIM];
__device__ __nv_bfloat16 g_f2h[ROWS_TOTAL * CDIM], g_f2l[ROWS_TOTAL * CDIM];
__device__ __nv_bfloat16 g_wqh[CDIM * CDIM],       g_wql[CDIM * CDIM];
__device__ __nv_bfloat16 g_wph[CDIM * CDIM],       g_wpl[CDIM * CDIM];
__device__ __half        g_qF [ROWS_TOTAL * CDIM];                      // fp16, pre-scaled
__device__ __half        g_kvH[ROWS_TOTAL * CDIM], g_kvL[ROWS_TOTAL * CDIM]; // fp16 hi/lo
__device__ __nv_bfloat16 g_xh [ROWS_TOTAL * CDIM], g_xl [ROWS_TOTAL * CDIM];

// ---------------------------------------------------------------------------
__device__ __forceinline__ uint32_t smem_u32(const void* p) {
    uint32_t a;
    asm("{ .reg .u64 t; cvta.to.shared.u64 t, %1; cvt.u32.u64 %0, t; }"
        : "=r"(a) : "l"(p));
    return a;
}

#define CP16(dst, src)                                                        \
    asm volatile("cp.async.cg.shared.global [%0], [%1], 16;"                  \
                 :: "r"(dst), "l"(src) : "memory")
#define CP_COMMIT() asm volatile("cp.async.commit_group;" ::: "memory")
#define CP_WAIT1()  asm volatile("cp.async.wait_group 1;" ::: "memory")
#define CP_WAIT0()  asm volatile("cp.async.wait_group 0;" ::: "memory")
#define BARG(id)                                                              \
    asm volatile("bar.sync %0, 256;" :: "r"(id) : "memory")

#define LDSM_X4(R0, R1, R2, R3, A)                                            \
    asm volatile("ldmatrix.sync.aligned.m8n8.x4.shared.b16 {%0,%1,%2,%3}, [%4];" \
                 : "=r"(R0), "=r"(R1), "=r"(R2), "=r"(R3) : "r"(A))
#define LDSM_X4T(R0, R1, R2, R3, A)                                           \
    asm volatile("ldmatrix.sync.aligned.m8n8.x4.trans.shared.b16 {%0,%1,%2,%3}, [%4];" \
                 : "=r"(R0), "=r"(R1), "=r"(R2), "=r"(R3) : "r"(A))
// bf16 MMA (GEMMs)
#define MMA_BF(D, A0, A1, A2, A3, B0, B1)                                     \
    asm volatile("mma.sync.aligned.m16n8k16.row.col.f32.bf16.bf16.f32 "       \
                 "{%0,%1,%2,%3}, {%4,%5,%6,%7}, {%8,%9}, {%0,%1,%2,%3};"      \
                 : "+f"((D)[0]), "+f"((D)[1]), "+f"((D)[2]), "+f"((D)[3])     \
                 : "r"(A0), "r"(A1), "r"(A2), "r"(A3), "r"(B0), "r"(B1))
// fp16 MMA (attention)
#define MMA_FP(D, A0, A1, A2, A3, B0, B1)                                     \
    asm volatile("mma.sync.aligned.m16n8k16.row.col.f32.f16.f16.f32 "         \
                 "{%0,%1,%2,%3}, {%4,%5,%6,%7}, {%8,%9}, {%0,%1,%2,%3};"      \
                 : "+f"((D)[0]), "+f"((D)[1]), "+f"((D)[2]), "+f"((D)[3])     \
                 : "r"(A0), "r"(A1), "r"(A2), "r"(A3), "r"(B0), "r"(B1))

__device__ __forceinline__ uint32_t b2u(__nv_bfloat162 h) { return *(uint32_t*)&h; }
__device__ __forceinline__ uint32_t h2u(__half2 h) { return *(uint32_t*)&h; }

// ============================ conversion: fp32 -> bf16 hi/lo =================
__global__ void conv_split(const float4* __restrict__ src, uint2* __restrict__ h,
                           uint2* __restrict__ l, int n4) {
    for (int i = blockIdx.x * blockDim.x + threadIdx.x; i < n4;
         i += gridDim.x * blockDim.x) {
        float4 v = src[i];
        __nv_bfloat162 h0 = __floats2bfloat162_rn(v.x, v.y);
        __nv_bfloat162 h1 = __floats2bfloat162_rn(v.z, v.w);
        __nv_bfloat162 l0 = __floats2bfloat162_rn(v.x - __bfloat162float(h0.x),
                                                  v.y - __bfloat162float(h0.y));
        __nv_bfloat162 l1 = __floats2bfloat162_rn(v.z - __bfloat162float(h1.x),
                                                  v.w - __bfloat162float(h1.y));
        h[i] = make_uint2(b2u(h0), b2u(h1));
        l[i] = make_uint2(b2u(l0), b2u(l1));
    }
}

// ============================ GEMM + bias (bf16 3-term) ======================
// CTA tile 256x128, 512 threads, K-chunk 64, cp.async double-buffered.
// mode 0: fp32 out; mode 1: fp16 single (scaled) -> Hc; mode 2: fp16 hi/lo pair.
#define ASTR 144
#define A_SPLIT 36864
#define A_STAGE (2 * A_SPLIT)
#define WSTR 272
#define W_SPLIT 17408
#define W_STAGE (2 * W_SPLIT)
#define GW_BASE (2 * A_STAGE)
#define G_SMEM (GW_BASE + 2 * W_STAGE)   // 217088

__global__ void __launch_bounds__(512, 1)
gemm_tc(const __nv_bfloat16* __restrict__ Ah, const __nv_bfloat16* __restrict__ Al,
        const __nv_bfloat16* __restrict__ Wh, const __nv_bfloat16* __restrict__ Wl,
        const float* __restrict__ bias, float* __restrict__ C,
        __half* __restrict__ Hc, __half* __restrict__ Lc,
        float scale, int mode) {
    extern __shared__ char sm[];
    const uint32_t sb = smem_u32(sm);
    const int tid = threadIdx.x, l = tid & 31, wid = tid >> 5;
    const int row0 = blockIdx.y * 256, col0 = blockIdx.x * 128;
    const int wm = wid >> 2, wn = wid & 3;

    const uint32_t a_boff = (uint32_t)(wm * 64 + (l & 15)) * ASTR + ((l >> 4) & 1) * 16;
    const uint32_t b_boff = (uint32_t)((l & 7) + ((l >> 3) & 1) * 8) * WSTR +
                            ((l >> 4) & 1) * 16 + (uint32_t)wn * 64;

    auto issue = [&](int ch, int buf) {
#pragma unroll
        for (int t = 0; t < 4; t++) {
            int idx = tid + t * 512, r = idx >> 3, ai = idx & 7;
            uint32_t d = sb + buf * A_STAGE + (uint32_t)r * ASTR + ai * 16;
            const __nv_bfloat16* s = Ah + (size_t)(row0 + r) * CDIM + ch * 64 + ai * 8;
            CP16(d, s);
            CP16(d + A_SPLIT, Al + (s - Ah));
        }
#pragma unroll
        for (int t = 0; t < 2; t++) {
            int idx = tid + t * 512, r = idx >> 4, wi = idx & 15;
            uint32_t d = sb + GW_BASE + buf * W_STAGE + (uint32_t)r * WSTR + wi * 16;
            const __nv_bfloat16* s = Wh + (size_t)(ch * 64 + r) * CDIM + col0 + wi * 8;
            CP16(d, s);
            CP16(d + W_SPLIT, Wl + (s - Wh));
        }
        CP_COMMIT();
    };

    float acc[4][4][4];
#pragma unroll
    for (int i = 0; i < 4; i++)
#pragma unroll
        for (int j = 0; j < 4; j++)
#pragma unroll
            for (int e = 0; e < 4; e++) acc[i][j][e] = 0.0f;

    issue(0, 0);
    for (int ch = 0; ch < 8; ch++) {
        const int cur = ch & 1;
        if (ch < 7) issue(ch + 1, cur ^ 1);
        if (ch < 7) CP_WAIT1(); else CP_WAIT0();
        __syncthreads();

        const uint32_t AH = sb + cur * A_STAGE, AL = AH + A_SPLIT;
        const uint32_t WH = sb + GW_BASE + cur * W_STAGE, WL = WH + W_SPLIT;
#pragma unroll
        for (int t = 0; t < 4; t++) {
            uint32_t aH[4][4], aL[4][4];
#pragma unroll
            for (int i = 0; i < 4; i++) {
                LDSM_X4(aH[i][0], aH[i][1], aH[i][2], aH[i][3],
                        AH + a_boff + i * 16 * ASTR + t * 32);
                LDSM_X4(aL[i][0], aL[i][1], aL[i][2], aL[i][3],
                        AL + a_boff + i * 16 * ASTR + t * 32);
            }
#pragma unroll
            for (int c2 = 0; c2 < 2; c2++) {
                uint32_t bh0, bh1, bh2, bh3, bl0, bl1, bl2, bl3;
                LDSM_X4T(bh0, bh1, bh2, bh3, WH + b_boff + t * 16 * WSTR + c2 * 32);
                LDSM_X4T(bl0, bl1, bl2, bl3, WL + b_boff + t * 16 * WSTR + c2 * 32);
#pragma unroll
                for (int i = 0; i < 4; i++) {
                    MMA_BF(acc[i][c2 * 2 + 0], aH[i][0], aH[i][1], aH[i][2], aH[i][3], bh0, bh1);
                    MMA_BF(acc[i][c2 * 2 + 1], aH[i][0], aH[i][1], aH[i][2], aH[i][3], bh2, bh3);
                    MMA_BF(acc[i][c2 * 2 + 0], aH[i][0], aH[i][1], aH[i][2], aH[i][3], bl0, bl1);
                    MMA_BF(acc[i][c2 * 2 + 1], aH[i][0], aH[i][1], aH[i][2], aH[i][3], bl2, bl3);
                    MMA_BF(acc[i][c2 * 2 + 0], aL[i][0], aL[i][1], aL[i][2], aL[i][3], bh0, bh1);
                    MMA_BF(acc[i][c2 * 2 + 1], aL[i][0], aL[i][1], aL[i][2], aL[i][3], bh2, bh3);
                }
            }
        }
        __syncthreads();
    }

    // epilogue
#pragma unroll
    for (int i = 0; i < 4; i++)
#pragma unroll
        for (int j = 0; j < 4; j++) {
            int r = row0 + wm * 64 + i * 16 + (l >> 2);
            int c = col0 + wn * 32 + j * 8 + (l & 3) * 2;
            float2 bb = *(const float2*)(bias + c);
            float v0 = acc[i][j][0] + bb.x, v1 = acc[i][j][1] + bb.y;
            float v2 = acc[i][j][2] + bb.x, v3 = acc[i][j][3] + bb.y;
            if (mode == 0) {
                *(float2*)(C + (size_t)r * CDIM + c)       = make_float2(v0, v1);
                *(float2*)(C + (size_t)(r + 8) * CDIM + c) = make_float2(v2, v3);
            } else if (mode == 1) {      // fp16 single, scaled (Q)
                *(uint32_t*)(Hc + (size_t)r * CDIM + c) =
                    h2u(__floats2half2_rn(v0 * scale, v1 * scale));
                *(uint32_t*)(Hc + (size_t)(r + 8) * CDIM + c) =
                    h2u(__floats2half2_rn(v2 * scale, v3 * scale));
            } else {                     // fp16 hi/lo pair (KV)
                __half2 h0 = __floats2half2_rn(v0, v1);
                __half2 h1 = __floats2half2_rn(v2, v3);
                __half2 l0 = __floats2half2_rn(v0 - __half2float(h0.x),
                                               v1 - __half2float(h0.y));
                __half2 l1 = __floats2half2_rn(v2 - __half2float(h1.x),
                                               v3 - __half2float(h1.y));
                *(uint32_t*)(Hc + (size_t)r * CDIM + c)       = h2u(h0);
                *(uint32_t*)(Hc + (size_t)(r + 8) * CDIM + c) = h2u(h1);
                *(uint32_t*)(Lc + (size_t)r * CDIM + c)       = h2u(l0);
                *(uint32_t*)(Lc + (size_t)(r + 8) * CDIM + c) = h2u(l1);
            }
        }
}

// ============================ Fused attention (fp16 2-term) ==================
// CTA per (b,h,128-q tile), 512 threads, 2 key-groups of 8 warps.
// S = Q_f16 . (K_hi + K_lo)^T ; PV: O += P_f16 . (V_hi + V_lo).
#define QSTR 272
#define Q_TILE 34816             // 128 rows x 256B fp16 (stride 272)
#define KSTR 272
#define K_SPLIT 17408            // 64 rows fp16
#define AK_BASE Q_TILE           // 34816
#define AT_SMEM (AK_BASE + 8 * K_SPLIT)   // 174080

__global__ void __launch_bounds__(512, 1)
attn_tc(const __half* __restrict__ Qf,
        const __half* __restrict__ KVh, const __half* __restrict__ KVl,
        __nv_bfloat16* __restrict__ Xh, __nv_bfloat16* __restrict__ Xl) {
    extern __shared__ char sm[];
    const uint32_t sb = smem_u32(sm);
    const int tid = threadIdx.x, l = tid & 31, wid = tid >> 5;
    const int g = wid >> 3, wg = wid & 7, gtid = tid & 255;
    const int b = blockIdx.z, h = blockIdx.y, n0 = blockIdx.x * 128;

    const uint32_t qa_boff = (uint32_t)(wg * 16 + (l & 15)) * QSTR + ((l >> 4) & 1) * 16;
    const uint32_t kb_boff = (uint32_t)((l & 7) + ((l >> 4) & 1) * 8) * KSTR +
                             ((l >> 3) & 1) * 16;
    const uint32_t vb_boff = (uint32_t)((l & 7) + ((l >> 3) & 1) * 8) * KSTR +
                             ((l >> 4) & 1) * 16;
    const size_t kvrow0 = (size_t)b * SEQ * CDIM + h * HDIM;

    auto issue_kv = [&](int j, int buf) {
        const int m = 2 * j + g;
        const uint32_t slot = sb + AK_BASE + (uint32_t)(g * 2 + buf) * (2 * K_SPLIT);
#pragma unroll
        for (int t = 0; t < 4; t++) {
            int idx = gtid + t * 256, r = idx >> 4, i = idx & 15;
            uint32_t d = slot + (uint32_t)r * KSTR + i * 16;
            const __half* s = KVh + kvrow0 + (size_t)(m * 64 + r) * CDIM + i * 8;
            CP16(d, s);
            CP16(d + K_SPLIT, KVl + (s - KVh));
        }
        CP_COMMIT();
    };

    // Q tile (fp16 single) — own commit group; full-CTA sync before first read
#pragma unroll
    for (int t = 0; t < 4; t++) {
        int idx = tid + t * 512;
        int r = idx >> 4, i = idx & 15;
        uint32_t d = sb + (uint32_t)r * QSTR + i * 16;
        CP16(d, Qf + ((size_t)(b * SEQ + n0 + r)) * CDIM + h * HDIM + i * 8);
    }
    CP_COMMIT();
    issue_kv(0, 0);

    CP_WAIT1();
    __syncthreads();

    float oacc[16][4];
#pragma unroll
    for (int n = 0; n < 16; n++)
#pragma unroll
        for (int e = 0; e < 4; e++) oacc[n][e] = 0.0f;
    float lsum0 = 0.0f, lsum1 = 0.0f;

    for (int j = 0; j < 16; j++) {
        const int cur = j & 1;
        if (j < 15) issue_kv(j + 1, cur ^ 1);
        if (j < 15) CP_WAIT1(); else CP_WAIT0();
        BARG(g + 1);

        const uint32_t KH = sb + AK_BASE + (uint32_t)(g * 2 + cur) * (2 * K_SPLIT);
        const uint32_t KL = KH + K_SPLIT;

        // ---- S = Q . (K_hi + K_lo)^T  (16 x 64 per warp) ----
        float sacc[8][4];
#pragma unroll
        for (int n = 0; n < 8; n++)
#pragma unroll
            for (int e = 0; e < 4; e++) sacc[n][e] = 0.0f;
#pragma unroll
        for (int t = 0; t < 8; t++) {
            uint32_t a0, a1, a2, a3;
            LDSM_X4(a0, a1, a2, a3, sb + qa_boff + t * 32);
#pragma unroll
            for (int jj = 0; jj < 4; jj++) {
                uint32_t bh0, bh1, bh2, bh3, bl0, bl1, bl2, bl3;
                LDSM_X4(bh0, bh1, bh2, bh3, KH + kb_boff + jj * 16 * KSTR + t * 32);
                LDSM_X4(bl0, bl1, bl2, bl3, KL + kb_boff + jj * 16 * KSTR + t * 32);
                MMA_FP(sacc[2 * jj + 0], a0, a1, a2, a3, bh0, bh1);
                MMA_FP(sacc[2 * jj + 1], a0, a1, a2, a3, bh2, bh3);
                MMA_FP(sacc[2 * jj + 0], a0, a1, a2, a3, bl0, bl1);
                MMA_FP(sacc[2 * jj + 1], a0, a1, a2, a3, bl2, bl3);
            }
        }

        // ---- softmax (no max-sub); P fp16 packed into sacc[n][0..1] ----
#pragma unroll
        for (int n = 0; n < 8; n++) {
            float p0 = __expf(sacc[n][0]);
            float p1 = __expf(sacc[n][1]);
            float p2 = __expf(sacc[n][2]);
            float p3 = __expf(sacc[n][3]);
            lsum0 += p0 + p1;
            lsum1 += p2 + p3;
            sacc[n][0] = __uint_as_float(h2u(__floats2half2_rn(p0, p1)));
            sacc[n][1] = __uint_as_float(h2u(__floats2half2_rn(p2, p3)));
        }

        // ---- O += P . (V_hi + V_lo)  (V = same KV tile, trans view) ----
#pragma unroll
        for (int tp = 0; tp < 4; tp++) {
            uint32_t h0 = __float_as_uint(sacc[2 * tp][0]);
            uint32_t h1 = __float_as_uint(sacc[2 * tp][1]);
            uint32_t h2 = __float_as_uint(sacc[2 * tp + 1][0]);
            uint32_t h3 = __float_as_uint(sacc[2 * tp + 1][1]);
#pragma unroll
            for (int dd = 0; dd < 8; dd++) {
                uint32_t vh0, vh1, vh2, vh3, vl0, vl1, vl2, vl3;
                LDSM_X4T(vh0, vh1, vh2, vh3, KH + vb_boff + tp * 16 * KSTR + dd * 32);
                LDSM_X4T(vl0, vl1, vl2, vl3, KL + vb_boff + tp * 16 * KSTR + dd * 32);
                MMA_FP(oacc[2 * dd + 0], h0, h1, h2, h3, vh0, vh1);
                MMA_FP(oacc[2 * dd + 1], h0, h1, h2, h3, vh2, vh3);
                MMA_FP(oacc[2 * dd + 0], h0, h1, h2, h3, vl0, vl1);
                MMA_FP(oacc[2 * dd + 1], h0, h1, h2, h3, vl2, vl3);
            }
        }
        BARG(g + 1);
    }

    // row sums across the 4 threads sharing each row
    lsum0 += __shfl_xor_sync(0xffffffffu, lsum0, 1);
    lsum0 += __shfl_xor_sync(0xffffffffu, lsum0, 2);
    lsum1 += __shfl_xor_sync(0xffffffffu, lsum1, 1);
    lsum1 += __shfl_xor_sync(0xffffffffu, lsum1, 2);

    // ---- combine groups ----
    float* stage = (float*)(sm + AK_BASE);
    float* ls = stage + 128 * 132;
    const int r0 = wg * 16 + (l >> 2);

    __syncthreads();
    if (g == 1) {
#pragma unroll
        for (int n = 0; n < 16; n++) {
            int c = n * 8 + (l & 3) * 2;
            *(float2*)&stage[r0 * 132 + c]       = make_float2(oacc[n][0], oacc[n][1]);
            *(float2*)&stage[(r0 + 8) * 132 + c] = make_float2(oacc[n][2], oacc[n][3]);
        }
        if ((l & 3) == 0) { ls[r0] = lsum0; ls[r0 + 8] = lsum1; }
    }
    __syncthreads();
    if (g == 0) {
        const float inv0 = 1.0f / (lsum0 + ls[r0]);
        const float inv1 = 1.0f / (lsum1 + ls[r0 + 8]);
#pragma unroll
        for (int n = 0; n < 16; n++) {
            int c = n * 8 + (l & 3) * 2;
            float2 p0 = *(float2*)&stage[r0 * 132 + c];
            float2 p1 = *(float2*)&stage[(r0 + 8) * 132 + c];
            float v0 = (oacc[n][0] + p0.x) * inv0, v1 = (oacc[n][1] + p0.y) * inv0;
            float v2 = (oacc[n][2] + p1.x) * inv1, v3 = (oacc[n][3] + p1.y) * inv1;
            __nv_bfloat162 h0 = __floats2bfloat162_rn(v0, v1);
            __nv_bfloat162 h1 = __floats2bfloat162_rn(v2, v3);
            __nv_bfloat162 l0 = __floats2bfloat162_rn(v0 - __bfloat162float(h0.x),
                                                      v1 - __bfloat162float(h0.y));
            __nv_bfloat162 l1 = __floats2bfloat162_rn(v2 - __bfloat162float(h1.x),
                                                      v3 - __bfloat162float(h1.y));
            // stage X hi/lo in Q tile area + upper KV area (disjoint from 'stage')
            *(uint32_t*)(sm + r0 * QSTR + c * 2)           = b2u(h0);
            *(uint32_t*)(sm + (r0 + 8) * QSTR + c * 2)     = b2u(h1);
            *(uint32_t*)(sm + AK_BASE + 4 * K_SPLIT + r0 * QSTR + c * 2)       = b2u(l0);
            *(uint32_t*)(sm + AK_BASE + 4 * K_SPLIT + (r0 + 8) * QSTR + c * 2) = b2u(l1);
        }
    }
    __syncthreads();

    // coalesced copy-out of Xh/Xl
#pragma unroll
    for (int t = 0; t < 8; t++) {
        int idx = tid + t * 512;
        int a = idx >> 11, r = (idx >> 4) & 127, i = idx & 15;
        uint32_t src = (a ? (AK_BASE + 4 * K_SPLIT) : 0u) + (uint32_t)r * QSTR + i * 16;
        uint4 v = *(uint4*)(sm + src);
        __nv_bfloat16* base = a ? Xl : Xh;
        *(uint4*)(base + ((size_t)(b * SEQ + n0 + r)) * CDIM + h * HDIM + i * 8) = v;
    }
}

// ============================ launch ============================
extern "C" void kernel_launch(void* const* d_in, const int* in_sizes, int n_in,
                              void* d_out, int out_size) {
    const float* F1    = (const float*)d_in[0];
    const float* F2    = (const float*)d_in[1];
    const float* Wqkv  = (const float*)d_in[2];
    const float* bqkv  = (const float*)d_in[3];
    const float* Wproj = (const float*)d_in[4];
    const float* bproj = (const float*)d_in[5];
    float* out = (float*)d_out;

    __nv_bfloat16 *f1h, *f1l, *f2h, *f2l, *wqh, *wql, *wph, *wpl, *xh, *xl;
    __half *qf, *kvh, *kvl;
    cudaGetSymbolAddress((void**)&f1h, g_f1h); cudaGetSymbolAddress((void**)&f1l, g_f1l);
    cudaGetSymbolAddress((void**)&f2h, g_f2h); cudaGetSymbolAddress((void**)&f2l, g_f2l);
    cudaGetSymbolAddress((void**)&wqh, g_wqh); cudaGetSymbolAddress((void**)&wql, g_wql);
    cudaGetSymbolAddress((void**)&wph, g_wph); cudaGetSymbolAddress((void**)&wpl, g_wpl);
    cudaGetSymbolAddress((void**)&qf,  g_qF);
    cudaGetSymbolAddress((void**)&kvh, g_kvH); cudaGetSymbolAddress((void**)&kvl, g_kvL);
    cudaGetSymbolAddress((void**)&xh,  g_xh);  cudaGetSymbolAddress((void**)&xl,  g_xl);

    cudaFuncSetAttribute(gemm_tc, cudaFuncAttributeMaxDynamicSharedMemorySize, G_SMEM);
    cudaFuncSetAttribute(attn_tc, cudaFuncAttributeMaxDynamicSharedMemorySize, AT_SMEM);

    const int NF4 = ROWS_TOTAL * CDIM / 4, NW4 = CDIM * CDIM / 4;
    conv_split<<<2048, 256>>>((const float4*)F1, (uint2*)f1h, (uint2*)f1l, NF4);
    conv_split<<<2048, 256>>>((const float4*)F2, (uint2*)f2h, (uint2*)f2l, NF4);
    conv_split<<<256, 256>>>((const float4*)Wqkv, (uint2*)wqh, (uint2*)wql, NW4);
    conv_split<<<256, 256>>>((const float4*)Wproj, (uint2*)wph, (uint2*)wpl, NW4);

    dim3 ggrid(CDIM / 128, ROWS_TOTAL / 256);   // (4, 64)
    gemm_tc<<<ggrid, 512, G_SMEM>>>(f1h, f1l, wqh, wql, bqkv, nullptr,
                                    qf, nullptr, SCALE_F, 1);
    gemm_tc<<<ggrid, 512, G_SMEM>>>(f2h, f2l, wqh, wql, bqkv, nullptr,
                                    kvh, kvl, 1.0f, 2);

    dim3 agrid(SEQ / 128, HEADS, BATCH);        // (16, 4, 8)
    attn_tc<<<agrid, 512, AT_SMEM>>>(qf, kvh, kvl, xh, xl);

    gemm_tc<<<ggrid, 512, G_SMEM>>>(xh, xl, wph, wpl, bproj, out,
                                    nullptr, nullptr, 0.0f, 0);
}

// round 15
// speedup vs baseline: 1.5508x; 1.2511x over previous
#include <cuda_runtime.h>
#include <cuda_fp16.h>
#include <cstdint>

#define BATCH 8
#define SEQ 2048
#define CDIM 512
#define HEADS 4
#define HDIM 128
#define ROWS_TOTAL (BATCH * SEQ)
#define SCALE_F 0.04419417382415922f   // 1/sqrt(512)

// ---------------- scratch (no cudaMalloc allowed) ----------
__device__ __half g_f1h[ROWS_TOTAL * CDIM], g_f1l[ROWS_TOTAL * CDIM]; // fp16 pair
__device__ __half g_f2h[ROWS_TOTAL * CDIM], g_f2l[ROWS_TOTAL * CDIM];
__device__ __half g_wq [CDIM * CDIM];                                 // fp16 single
__device__ __half g_wp [CDIM * CDIM];
__device__ __half g_qF [ROWS_TOTAL * CDIM];                           // fp16, pre-scaled
__device__ __half g_kvH[ROWS_TOTAL * CDIM], g_kvL[ROWS_TOTAL * CDIM]; // fp16 pair
__device__ __half g_xh [ROWS_TOTAL * CDIM], g_xl [ROWS_TOTAL * CDIM]; // fp16 pair

// ---------------------------------------------------------------------------
__device__ __forceinline__ uint32_t smem_u32(const void* p) {
    uint32_t a;
    asm("{ .reg .u64 t; cvta.to.shared.u64 t, %1; cvt.u32.u64 %0, t; }"
        : "=r"(a) : "l"(p));
    return a;
}

#define CP16(dst, src)                                                        \
    asm volatile("cp.async.cg.shared.global [%0], [%1], 16;"                  \
                 :: "r"(dst), "l"(src) : "memory")
#define CP_COMMIT() asm volatile("cp.async.commit_group;" ::: "memory")
#define CP_WAIT1()  asm volatile("cp.async.wait_group 1;" ::: "memory")
#define CP_WAIT0()  asm volatile("cp.async.wait_group 0;" ::: "memory")
#define BARG(id)                                                              \
    asm volatile("bar.sync %0, 256;" :: "r"(id) : "memory")

#define LDSM_X4(R0, R1, R2, R3, A)                                            \
    asm volatile("ldmatrix.sync.aligned.m8n8.x4.shared.b16 {%0,%1,%2,%3}, [%4];" \
                 : "=r"(R0), "=r"(R1), "=r"(R2), "=r"(R3) : "r"(A))
#define LDSM_X4T(R0, R1, R2, R3, A)                                           \
    asm volatile("ldmatrix.sync.aligned.m8n8.x4.trans.shared.b16 {%0,%1,%2,%3}, [%4];" \
                 : "=r"(R0), "=r"(R1), "=r"(R2), "=r"(R3) : "r"(A))
#define MMA_FP(D, A0, A1, A2, A3, B0, B1)                                     \
    asm volatile("mma.sync.aligned.m16n8k16.row.col.f32.f16.f16.f32 "         \
                 "{%0,%1,%2,%3}, {%4,%5,%6,%7}, {%8,%9}, {%0,%1,%2,%3};"      \
                 : "+f"((D)[0]), "+f"((D)[1]), "+f"((D)[2]), "+f"((D)[3])     \
                 : "r"(A0), "r"(A1), "r"(A2), "r"(A3), "r"(B0), "r"(B1))

__device__ __forceinline__ uint32_t h2u(__half2 h) { return *(uint32_t*)&h; }

// ============================ conversions ====================================
__global__ void conv_pair(const float4* __restrict__ src, uint2* __restrict__ h,
                          uint2* __restrict__ l, int n4) {
    for (int i = blockIdx.x * blockDim.x + threadIdx.x; i < n4;
         i += gridDim.x * blockDim.x) {
        float4 v = src[i];
        __half2 h0 = __floats2half2_rn(v.x, v.y);
        __half2 h1 = __floats2half2_rn(v.z, v.w);
        __half2 l0 = __floats2half2_rn(v.x - __half2float(h0.x),
                                       v.y - __half2float(h0.y));
        __half2 l1 = __floats2half2_rn(v.z - __half2float(h1.x),
                                       v.w - __half2float(h1.y));
        h[i] = make_uint2(h2u(h0), h2u(h1));
        l[i] = make_uint2(h2u(l0), h2u(l1));
    }
}

__global__ void conv_single(const float4* __restrict__ src, uint2* __restrict__ h,
                            int n4) {
    for (int i = blockIdx.x * blockDim.x + threadIdx.x; i < n4;
         i += gridDim.x * blockDim.x) {
        float4 v = src[i];
        h[i] = make_uint2(h2u(__floats2half2_rn(v.x, v.y)),
                          h2u(__floats2half2_rn(v.z, v.w)));
    }
}

// ============================ GEMM + bias (fp16, 2-MMA) ======================
// C = A @ W + bias;  A = (Ah + Al) fp16 pair, W = fp16 single (dropped A*W_err
// term ~2.8e-4 rel). CTA tile 256x128, 512 threads, K-chunk 64, cp.async DB.
// mode 0: fp32 out; mode 1: fp16 single scaled; mode 2: fp16 hi/lo pair.
#define ASTR 144
#define A_SPLIT 36864            // 256 rows * 144B
#define A_STAGE (2 * A_SPLIT)
#define WSTR 272
#define W_TILE 17408             // 64 rows * 272B (single)
#define GW_BASE (2 * A_STAGE)    // 147456
#define G_SMEM (GW_BASE + 2 * W_TILE)   // 182272

__global__ void __launch_bounds__(512, 1)
gemm_tc(const __half* __restrict__ Ah, const __half* __restrict__ Al,
        const __half* __restrict__ W, const float* __restrict__ bias,
        float* __restrict__ C, __half* __restrict__ Hc, __half* __restrict__ Lc,
        float scale, int mode) {
    extern __shared__ char sm[];
    const uint32_t sb = smem_u32(sm);
    const int tid = threadIdx.x, l = tid & 31, wid = tid >> 5;
    const int row0 = blockIdx.y * 256, col0 = blockIdx.x * 128;
    const int wm = wid >> 2, wn = wid & 3;

    const uint32_t a_boff = (uint32_t)(wm * 64 + (l & 15)) * ASTR + ((l >> 4) & 1) * 16;
    const uint32_t b_boff = (uint32_t)((l & 7) + ((l >> 3) & 1) * 8) * WSTR +
                            ((l >> 4) & 1) * 16 + (uint32_t)wn * 64;

    auto issue = [&](int ch, int buf) {
#pragma unroll
        for (int t = 0; t < 4; t++) {
            int idx = tid + t * 512, r = idx >> 3, ai = idx & 7;
            uint32_t d = sb + buf * A_STAGE + (uint32_t)r * ASTR + ai * 16;
            const __half* s = Ah + (size_t)(row0 + r) * CDIM + ch * 64 + ai * 8;
            CP16(d, s);
            CP16(d + A_SPLIT, Al + (s - Ah));
        }
#pragma unroll
        for (int t = 0; t < 2; t++) {
            int idx = tid + t * 512, r = idx >> 4, wi = idx & 15;
            uint32_t d = sb + GW_BASE + buf * W_TILE + (uint32_t)r * WSTR + wi * 16;
            CP16(d, W + (size_t)(ch * 64 + r) * CDIM + col0 + wi * 8);
        }
        CP_COMMIT();
    };

    float acc[4][4][4];
#pragma unroll
    for (int i = 0; i < 4; i++)
#pragma unroll
        for (int j = 0; j < 4; j++)
#pragma unroll
            for (int e = 0; e < 4; e++) acc[i][j][e] = 0.0f;

    issue(0, 0);
    for (int ch = 0; ch < 8; ch++) {
        const int cur = ch & 1;
        if (ch < 7) issue(ch + 1, cur ^ 1);
        if (ch < 7) CP_WAIT1(); else CP_WAIT0();
        __syncthreads();

        const uint32_t AH = sb + cur * A_STAGE, AL = AH + A_SPLIT;
        const uint32_t WB = sb + GW_BASE + cur * W_TILE;
#pragma unroll
        for (int t = 0; t < 4; t++) {
            uint32_t aH[4][4], aL[4][4];
#pragma unroll
            for (int i = 0; i < 4; i++) {
                LDSM_X4(aH[i][0], aH[i][1], aH[i][2], aH[i][3],
                        AH + a_boff + i * 16 * ASTR + t * 32);
                LDSM_X4(aL[i][0], aL[i][1], aL[i][2], aL[i][3],
                        AL + a_boff + i * 16 * ASTR + t * 32);
            }
#pragma unroll
            for (int c2 = 0; c2 < 2; c2++) {
                uint32_t b0, b1, b2, b3;
                LDSM_X4T(b0, b1, b2, b3, WB + b_boff + t * 16 * WSTR + c2 * 32);
#pragma unroll
                for (int i = 0; i < 4; i++) {
                    MMA_FP(acc[i][c2 * 2 + 0], aH[i][0], aH[i][1], aH[i][2], aH[i][3], b0, b1);
                    MMA_FP(acc[i][c2 * 2 + 1], aH[i][0], aH[i][1], aH[i][2], aH[i][3], b2, b3);
                    MMA_FP(acc[i][c2 * 2 + 0], aL[i][0], aL[i][1], aL[i][2], aL[i][3], b0, b1);
                    MMA_FP(acc[i][c2 * 2 + 1], aL[i][0], aL[i][1], aL[i][2], aL[i][3], b2, b3);
                }
            }
        }
        __syncthreads();
    }

    // epilogue
#pragma unroll
    for (int i = 0; i < 4; i++)
#pragma unroll
        for (int j = 0; j < 4; j++) {
            int r = row0 + wm * 64 + i * 16 + (l >> 2);
            int c = col0 + wn * 32 + j * 8 + (l & 3) * 2;
            float2 bb = *(const float2*)(bias + c);
            float v0 = acc[i][j][0] + bb.x, v1 = acc[i][j][1] + bb.y;
            float v2 = acc[i][j][2] + bb.x, v3 = acc[i][j][3] + bb.y;
            if (mode == 0) {
                *(float2*)(C + (size_t)r * CDIM + c)       = make_float2(v0, v1);
                *(float2*)(C + (size_t)(r + 8) * CDIM + c) = make_float2(v2, v3);
            } else if (mode == 1) {      // fp16 single, scaled (Q)
                *(uint32_t*)(Hc + (size_t)r * CDIM + c) =
                    h2u(__floats2half2_rn(v0 * scale, v1 * scale));
                *(uint32_t*)(Hc + (size_t)(r + 8) * CDIM + c) =
                    h2u(__floats2half2_rn(v2 * scale, v3 * scale));
            } else {                     // fp16 hi/lo pair (KV)
                __half2 h0 = __floats2half2_rn(v0, v1);
                __half2 h1 = __floats2half2_rn(v2, v3);
                __half2 l0 = __floats2half2_rn(v0 - __half2float(h0.x),
                                               v1 - __half2float(h0.y));
                __half2 l1 = __floats2half2_rn(v2 - __half2float(h1.x),
                                               v3 - __half2float(h1.y));
                *(uint32_t*)(Hc + (size_t)r * CDIM + c)       = h2u(h0);
                *(uint32_t*)(Hc + (size_t)(r + 8) * CDIM + c) = h2u(h1);
                *(uint32_t*)(Lc + (size_t)r * CDIM + c)       = h2u(l0);
                *(uint32_t*)(Lc + (size_t)(r + 8) * CDIM + c) = h2u(l1);
            }
        }
}

// ============================ Fused attention ================================
// CTA per (b,h,128-q tile), 512 threads, 2 key-groups of 8 warps.
// S = Q_f16 . K_hi^T (K_lo dropped: logit abs err ~5e-5, softmax-damped);
// PV: O += P_f16 . (V_hi + V_lo)  (V error passes 1:1, keep 2-term).
#define QSTR 272
#define Q_TILE 34816             // 128 rows x 256B fp16 (stride 272)
#define KSTR 272
#define K_SPLIT 17408            // 64 rows fp16
#define AK_BASE Q_TILE           // 34816
#define AT_SMEM (AK_BASE + 8 * K_SPLIT)   // 174080

__global__ void __launch_bounds__(512, 1)
attn_tc(const __half* __restrict__ Qf,
        const __half* __restrict__ KVh, const __half* __restrict__ KVl,
        __half* __restrict__ Xh, __half* __restrict__ Xl) {
    extern __shared__ char sm[];
    const uint32_t sb = smem_u32(sm);
    const int tid = threadIdx.x, l = tid & 31, wid = tid >> 5;
    const int g = wid >> 3, wg = wid & 7, gtid = tid & 255;
    const int b = blockIdx.z, h = blockIdx.y, n0 = blockIdx.x * 128;

    const uint32_t qa_boff = (uint32_t)(wg * 16 + (l & 15)) * QSTR + ((l >> 4) & 1) * 16;
    const uint32_t kb_boff = (uint32_t)((l & 7) + ((l >> 4) & 1) * 8) * KSTR +
                             ((l >> 3) & 1) * 16;
    const uint32_t vb_boff = (uint32_t)((l & 7) + ((l >> 3) & 1) * 8) * KSTR +
                             ((l >> 4) & 1) * 16;
    const size_t kvrow0 = (size_t)b * SEQ * CDIM + h * HDIM;

    auto issue_kv = [&](int j, int buf) {
        const int m = 2 * j + g;
        const uint32_t slot = sb + AK_BASE + (uint32_t)(g * 2 + buf) * (2 * K_SPLIT);
#pragma unroll
        for (int t = 0; t < 4; t++) {
            int idx = gtid + t * 256, r = idx >> 4, i = idx & 15;
            uint32_t d = slot + (uint32_t)r * KSTR + i * 16;
            const __half* s = KVh + kvrow0 + (size_t)(m * 64 + r) * CDIM + i * 8;
            CP16(d, s);
            CP16(d + K_SPLIT, KVl + (s - KVh));
        }
        CP_COMMIT();
    };

    // Q tile (fp16 single) — own commit group; full-CTA sync before first read
#pragma unroll
    for (int t = 0; t < 4; t++) {
        int idx = tid + t * 512;
        int r = idx >> 4, i = idx & 15;
        uint32_t d = sb + (uint32_t)r * QSTR + i * 16;
        CP16(d, Qf + ((size_t)(b * SEQ + n0 + r)) * CDIM + h * HDIM + i * 8);
    }
    CP_COMMIT();
    issue_kv(0, 0);

    CP_WAIT1();
    __syncthreads();

    float oacc[16][4];
#pragma unroll
    for (int n = 0; n < 16; n++)
#pragma unroll
        for (int e = 0; e < 4; e++) oacc[n][e] = 0.0f;
    float lsum0 = 0.0f, lsum1 = 0.0f;

    for (int j = 0; j < 16; j++) {
        const int cur = j & 1;
        if (j < 15) issue_kv(j + 1, cur ^ 1);
        if (j < 15) CP_WAIT1(); else CP_WAIT0();
        BARG(g + 1);

        const uint32_t KH = sb + AK_BASE + (uint32_t)(g * 2 + cur) * (2 * K_SPLIT);
        const uint32_t KL = KH + K_SPLIT;

        // ---- S = Q . K_hi^T  (16 x 64 per warp; K_lo dropped) ----
        float sacc[8][4];
#pragma unroll
        for (int n = 0; n < 8; n++)
#pragma unroll
            for (int e = 0; e < 4; e++) sacc[n][e] = 0.0f;
#pragma unroll
        for (int t = 0; t < 8; t++) {
            uint32_t a0, a1, a2, a3;
            LDSM_X4(a0, a1, a2, a3, sb + qa_boff + t * 32);
#pragma unroll
            for (int jj = 0; jj < 4; jj++) {
                uint32_t bh0, bh1, bh2, bh3;
                LDSM_X4(bh0, bh1, bh2, bh3, KH + kb_boff + jj * 16 * KSTR + t * 32);
                MMA_FP(sacc[2 * jj + 0], a0, a1, a2, a3, bh0, bh1);
                MMA_FP(sacc[2 * jj + 1], a0, a1, a2, a3, bh2, bh3);
            }
        }

        // ---- softmax (no max-sub); P fp16 packed into sacc[n][0..1] ----
#pragma unroll
        for (int n = 0; n < 8; n++) {
            float p0 = __expf(sacc[n][0]);
            float p1 = __expf(sacc[n][1]);
            float p2 = __expf(sacc[n][2]);
            float p3 = __expf(sacc[n][3]);
            lsum0 += p0 + p1;
            lsum1 += p2 + p3;
            sacc[n][0] = __uint_as_float(h2u(__floats2half2_rn(p0, p1)));
            sacc[n][1] = __uint_as_float(h2u(__floats2half2_rn(p2, p3)));
        }

        // ---- O += P . (V_hi + V_lo)  (V = same KV tile, trans view) ----
#pragma unroll
        for (int tp = 0; tp < 4; tp++) {
            uint32_t h0 = __float_as_uint(sacc[2 * tp][0]);
            uint32_t h1 = __float_as_uint(sacc[2 * tp][1]);
            uint32_t h2 = __float_as_uint(sacc[2 * tp + 1][0]);
            uint32_t h3 = __float_as_uint(sacc[2 * tp + 1][1]);
#pragma unroll
            for (int dd = 0; dd < 8; dd++) {
                uint32_t vh0, vh1, vh2, vh3, vl0, vl1, vl2, vl3;
                LDSM_X4T(vh0, vh1, vh2, vh3, KH + vb_boff + tp * 16 * KSTR + dd * 32);
                LDSM_X4T(vl0, vl1, vl2, vl3, KL + vb_boff + tp * 16 * KSTR + dd * 32);
                MMA_FP(oacc[2 * dd + 0], h0, h1, h2, h3, vh0, vh1);
                MMA_FP(oacc[2 * dd + 1], h0, h1, h2, h3, vh2, vh3);
                MMA_FP(oacc[2 * dd + 0], h0, h1, h2, h3, vl0, vl1);
                MMA_FP(oacc[2 * dd + 1], h0, h1, h2, h3, vl2, vl3);
            }
        }
        BARG(g + 1);
    }

    // row sums across the 4 threads sharing each row
    lsum0 += __shfl_xor_sync(0xffffffffu, lsum0, 1);
    lsum0 += __shfl_xor_sync(0xffffffffu, lsum0, 2);
    lsum1 += __shfl_xor_sync(0xffffffffu, lsum1, 1);
    lsum1 += __shfl_xor_sync(0xffffffffu, lsum1, 2);

    // ---- combine groups ----
    float* stage = (float*)(sm + AK_BASE);
    float* ls = stage + 128 * 132;
    const int r0 = wg * 16 + (l >> 2);

    __syncthreads();
    if (g == 1) {
#pragma unroll
        for (int n = 0; n < 16; n++) {
            int c = n * 8 + (l & 3) * 2;
            *(float2*)&stage[r0 * 132 + c]       = make_float2(oacc[n][0], oacc[n][1]);
            *(float2*)&stage[(r0 + 8) * 132 + c] = make_float2(oacc[n][2], oacc[n][3]);
        }
        if ((l & 3) == 0) { ls[r0] = lsum0; ls[r0 + 8] = lsum1; }
    }
    __syncthreads();
    if (g == 0) {
        const float inv0 = 1.0f / (lsum0 + ls[r0]);
        const float inv1 = 1.0f / (lsum1 + ls[r0 + 8]);
#pragma unroll
        for (int n = 0; n < 16; n++) {
            int c = n * 8 + (l & 3) * 2;
            float2 p0 = *(float2*)&stage[r0 * 132 + c];
            float2 p1 = *(float2*)&stage[(r0 + 8) * 132 + c];
            float v0 = (oacc[n][0] + p0.x) * inv0, v1 = (oacc[n][1] + p0.y) * inv0;
            float v2 = (oacc[n][2] + p1.x) * inv1, v3 = (oacc[n][3] + p1.y) * inv1;
            __half2 h0 = __floats2half2_rn(v0, v1);
            __half2 h1 = __floats2half2_rn(v2, v3);
            __half2 l0 = __floats2half2_rn(v0 - __half2float(h0.x),
                                           v1 - __half2float(h0.y));
            __half2 l1 = __floats2half2_rn(v2 - __half2float(h1.x),
                                           v3 - __half2float(h1.y));
            *(uint32_t*)(sm + r0 * QSTR + c * 2)           = h2u(h0);
            *(uint32_t*)(sm + (r0 + 8) * QSTR + c * 2)     = h2u(h1);
            *(uint32_t*)(sm + AK_BASE + 4 * K_SPLIT + r0 * QSTR + c * 2)       = h2u(l0);
            *(uint32_t*)(sm + AK_BASE + 4 * K_SPLIT + (r0 + 8) * QSTR + c * 2) = h2u(l1);
        }
    }
    __syncthreads();

    // coalesced copy-out of Xh/Xl
#pragma unroll
    for (int t = 0; t < 8; t++) {
        int idx = tid + t * 512;
        int a = idx >> 11, r = (idx >> 4) & 127, i = idx & 15;
        uint32_t src = (a ? (AK_BASE + 4 * K_SPLIT) : 0u) + (uint32_t)r * QSTR + i * 16;
        uint4 v = *(uint4*)(sm + src);
        __half* base = a ? Xl : Xh;
        *(uint4*)(base + ((size_t)(b * SEQ + n0 + r)) * CDIM + h * HDIM + i * 8) = v;
    }
}

// ============================ launch ============================
extern "C" void kernel_launch(void* const* d_in, const int* in_sizes, int n_in,
                              void* d_out, int out_size) {
    const float* F1    = (const float*)d_in[0];
    const float* F2    = (const float*)d_in[1];
    const float* Wqkv  = (const float*)d_in[2];
    const float* bqkv  = (const float*)d_in[3];
    const float* Wproj = (const float*)d_in[4];
    const float* bproj = (const float*)d_in[5];
    float* out = (float*)d_out;

    __half *f1h, *f1l, *f2h, *f2l, *wq, *wp, *qf, *kvh, *kvl, *xh, *xl;
    cudaGetSymbolAddress((void**)&f1h, g_f1h); cudaGetSymbolAddress((void**)&f1l, g_f1l);
    cudaGetSymbolAddress((void**)&f2h, g_f2h); cudaGetSymbolAddress((void**)&f2l, g_f2l);
    cudaGetSymbolAddress((void**)&wq,  g_wq);  cudaGetSymbolAddress((void**)&wp,  g_wp);
    cudaGetSymbolAddress((void**)&qf,  g_qF);
    cudaGetSymbolAddress((void**)&kvh, g_kvH); cudaGetSymbolAddress((void**)&kvl, g_kvL);
    cudaGetSymbolAddress((void**)&xh,  g_xh);  cudaGetSymbolAddress((void**)&xl,  g_xl);

    cudaFuncSetAttribute(gemm_tc, cudaFuncAttributeMaxDynamicSharedMemorySize, G_SMEM);
    cudaFuncSetAttribute(attn_tc, cudaFuncAttributeMaxDynamicSharedMemorySize, AT_SMEM);

    const int NF4 = ROWS_TOTAL * CDIM / 4, NW4 = CDIM * CDIM / 4;
    conv_pair<<<2048, 256>>>((const float4*)F1, (uint2*)f1h, (uint2*)f1l, NF4);
    conv_pair<<<2048, 256>>>((const float4*)F2, (uint2*)f2h, (uint2*)f2l, NF4);
    conv_single<<<256, 256>>>((const float4*)Wqkv, (uint2*)wq, NW4);
    conv_single<<<256, 256>>>((const float4*)Wproj, (uint2*)wp, NW4);

    dim3 ggrid(CDIM / 128, ROWS_TOTAL / 256);   // (4, 64)
    gemm_tc<<<ggrid, 512, G_SMEM>>>(f1h, f1l, wq, bqkv, nullptr,
                                    qf, nullptr, SCALE_F, 1);
    gemm_tc<<<ggrid, 512, G_SMEM>>>(f2h, f2l, wq, bqkv, nullptr,
                                    kvh, kvl, 1.0f, 2);

    dim3 agrid(SEQ / 128, HEADS, BATCH);        // (16, 4, 8)
    attn_tc<<<agrid, 512, AT_SMEM>>>(qf, kvh, kvl, xh, xl);

    gemm_tc<<<ggrid, 512, G_SMEM>>>(xh, xl, wp, bproj, out,
                                    nullptr, nullptr, 0.0f, 0);
}